// round 9
// baseline (speedup 1.0000x reference)
#include <cuda_runtime.h>
#include <cstdint>

// ProbMask: out[b,h,u,col] = (col > m_top[b,h,u]) ? 1.0f : 0.0f  (float32).
// rows = 32768, L_K = 4096 fp32 -> 512 MB of stores.
//
// Evidence so far:
//   R5 (STG.128 only):  3.8 TB/s, L1tex-funnel bound (~26 GB/s/SM).
//   R6 (TMA only, 4096 CTAs): 6.06 TB/s, 81.1 us.
//   R7 (TMA only, 256 CTAs): 44.1 GB/s/SM even with idle SMs -> per-SM TMA
//       store service cap ~= 44 GB/s. TMA-only ceiling ~6.5 TB/s chip-wide.
// This round: HYBRID. Each CTA handles 16 rows: 10 rows streamed via
// cp.async.bulk (TMA engine) + 6 rows via STG.E.128 (LSU/L1tex path).
// The two per-SM paths are independent (~44 + ~26 GB/s) and converge only at
// LTS/HBM, which showed no wall below ~7.5 TB/s. 2048 CTAs -> 1.2% imbalance.

static constexpr int L_K          = 4096;
static constexpr int ROW_BYTES    = L_K * 4;      // 16384
static constexpr int ROW_CHUNKS   = L_K / 4;      // 1024 float4 per row
static constexpr int ROWS_PER_CTA = 16;
static constexpr int TMA_ROWS     = 10;           // rows [0,10) via bulk copy
static constexpr int THREADS      = 512;

__global__ __launch_bounds__(THREADS)
void probmask_hybrid_kernel(const int* __restrict__ m_top, float* __restrict__ out) {
    __shared__ __align__(16) float zbuf[L_K];     // 16 KB of 0.0f
    __shared__ __align__(16) float obuf[L_K];     // 16 KB of 1.0f

    const int t = threadIdx.x;
    #pragma unroll
    for (int i = t; i < L_K; i += THREADS) { zbuf[i] = 0.f; obuf[i] = 1.f; }
    __syncthreads();
    // order generic-proxy SMEM writes before async-proxy (TMA) reads
    asm volatile("fence.proxy.async.shared::cta;" ::: "memory");
    __syncthreads();

    const int row0 = blockIdx.x * ROWS_PER_CTA;

    // ---- TMA path: threads 0..TMA_ROWS-1 each own one row; issue first so the
    // async engine streams while the rest of the CTA does STG work. ----
    bool issued = false;
    if (t < TMA_ROWS) {
        const int row = row0 + t;
        const int m   = __ldg(&m_top[row]);
        const int zb  = m + 1;                    // leading zero floats, [1, 4096]
        char* gdst = reinterpret_cast<char*>(out) + static_cast<size_t>(row) * ROW_BYTES;

        // boundary float4 patch (bytes disjoint from both bulk copies)
        if (zb & 3) {
            const int cb = zb >> 2;
            const int c0 = cb << 2;
            float4 v;
            v.x = (c0 + 0 > m) ? 1.f : 0.f;
            v.y = (c0 + 1 > m) ? 1.f : 0.f;
            v.z = (c0 + 2 > m) ? 1.f : 0.f;
            v.w = (c0 + 3 > m) ? 1.f : 0.f;
            reinterpret_cast<float4*>(gdst)[cb] = v;
        }

        const int zchunks = zb >> 2;
        const int ostart  = zchunks + ((zb & 3) ? 1 : 0);
        const uint32_t zbytes = static_cast<uint32_t>(zchunks) * 16u;
        const uint32_t obytes = static_cast<uint32_t>(ROW_CHUNKS - ostart) * 16u;
        const uint32_t zsrc = static_cast<uint32_t>(__cvta_generic_to_shared(zbuf));
        const uint32_t osrc = static_cast<uint32_t>(__cvta_generic_to_shared(obuf));

        if (zbytes)
            asm volatile("cp.async.bulk.global.shared::cta.bulk_group [%0], [%1], %2;"
                         :: "l"(gdst), "r"(zsrc), "r"(zbytes) : "memory");
        if (obytes)
            asm volatile("cp.async.bulk.global.shared::cta.bulk_group [%0], [%1], %2;"
                         :: "l"(gdst + static_cast<size_t>(ostart) * 16), "r"(osrc), "r"(obytes)
                         : "memory");
        asm volatile("cp.async.bulk.commit_group;" ::: "memory");
        issued = true;
    }

    // ---- STG path: all 512 threads cover rows [TMA_ROWS, 16), 8 floats each ----
    const int col0 = t << 3;                      // 512 threads x 8 floats = 4096
    #pragma unroll
    for (int r = TMA_ROWS; r < ROWS_PER_CTA; r++) {
        const int row = row0 + r;
        const int m   = __ldg(&m_top[row]);

        float4 v0, v1;
        if (col0 > m) {
            v0 = make_float4(1.f, 1.f, 1.f, 1.f);
            v1 = v0;
        } else if (col0 + 7 <= m) {
            v0 = make_float4(0.f, 0.f, 0.f, 0.f);
            v1 = v0;
        } else {
            v0.x = (col0 + 0 > m) ? 1.f : 0.f;
            v0.y = (col0 + 1 > m) ? 1.f : 0.f;
            v0.z = (col0 + 2 > m) ? 1.f : 0.f;
            v0.w = (col0 + 3 > m) ? 1.f : 0.f;
            v1.x = (col0 + 4 > m) ? 1.f : 0.f;
            v1.y = (col0 + 5 > m) ? 1.f : 0.f;
            v1.z = (col0 + 6 > m) ? 1.f : 0.f;
            v1.w = (col0 + 7 > m) ? 1.f : 0.f;
        }
        float4* row_out = reinterpret_cast<float4*>(out + static_cast<size_t>(row) * L_K);
        row_out[2 * t + 0] = v0;
        row_out[2 * t + 1] = v1;
    }

    // SMEM must stay alive until this thread's bulk copies complete.
    if (issued)
        asm volatile("cp.async.bulk.wait_group 0;" ::: "memory");
}

extern "C" void kernel_launch(void* const* d_in, const int* in_sizes, int n_in,
                              void* d_out, int out_size) {
    const int rows = out_size / L_K;              // 32768

    // m_top: the int32 input with exactly `rows` elements (metadata: d_in[1]).
    const int* m_top = reinterpret_cast<const int*>(d_in[1]);
    for (int i = 0; i < n_in; i++) {
        if (in_sizes[i] == rows) { m_top = reinterpret_cast<const int*>(d_in[i]); break; }
    }

    float* out = reinterpret_cast<float*>(d_out);
    probmask_hybrid_kernel<<<rows / ROWS_PER_CTA, THREADS>>>(m_top, out);
}

// round 11
// speedup vs baseline: 1.2870x; 1.2870x over previous
#include <cuda_runtime.h>
#include <cstdint>

// ProbMask: out[b,h,u,col] = (col > m_top[b,h,u]) ? 1.0f : 0.0f  (float32).
// rows = 32768, L_K = 4096 fp32 -> 512 MB of stores.
//
// Evidence: R5 STG-only 3.8 TB/s (L1tex-bound); R6 TMA-only 6.06 TB/s at a
// measured ~44 GB/s/SM TMA service cap (R7 confirmed cap with idle SMs);
// R9 hybrid regressed (TMA SMEM-reads and STG share L1tex in-SM).
// R10/R11: raise the per-SM TMA rate by HALVING op count: one 16 KB bulk copy
// per row instead of two. SMEM holds [16 KB zeros | 16 KB ones]; a row equals
// the 16 KB window at offset (16 KB - zbytes_rounded). The mixed boundary
// float4 (when (m+1) % 4 != 0) is patched with a single STG AFTER wait_group
// (copy and patch overlap bytes, so ordering is required).

static constexpr int L_K          = 4096;
static constexpr int ROW_BYTES    = L_K * 4;          // 16384
static constexpr int ROWS_PER_CTA = 8;
static constexpr int THREADS      = 128;

__global__ __launch_bounds__(THREADS)
void probmask_tma1_kernel(const int* __restrict__ m_top, float* __restrict__ out) {
    // [0, 4096) floats = 0.0f ; [4096, 8192) floats = 1.0f  (32 KB total)
    __shared__ __align__(128) float comb[2 * L_K];

    const int t = threadIdx.x;
    #pragma unroll
    for (int i = t; i < L_K; i += THREADS) {
        comb[i]       = 0.f;
        comb[L_K + i] = 1.f;
    }
    __syncthreads();
    // order generic-proxy SMEM writes before async-proxy (TMA) reads
    asm volatile("fence.proxy.async.shared::cta;" ::: "memory");
    __syncthreads();

    // Threads 0..7 each own one row end-to-end (bulk groups are per-thread).
    if (t < ROWS_PER_CTA) {
        const int row = blockIdx.x * ROWS_PER_CTA + t;
        const int m   = __ldg(&m_top[row]);
        const int zb  = m + 1;                        // leading zero floats, [1, 4096]
        const int zchunks = zb >> 2;                  // full zero float4s

        char* gdst = reinterpret_cast<char*>(out) + static_cast<size_t>(row) * ROW_BYTES;

        // One 16 KB copy: window [16KB - zchunks*16, +16KB) of comb is
        // zeros(zchunks*16) ++ ones(rest) — the whole row, with the mixed
        // chunk temporarily written as all-ones.
        const uint32_t src = static_cast<uint32_t>(__cvta_generic_to_shared(comb))
                           + static_cast<uint32_t>(ROW_BYTES - zchunks * 16);
        asm volatile("cp.async.bulk.global.shared::cta.bulk_group [%0], [%1], %2;"
                     :: "l"(gdst), "r"(src), "n"(ROW_BYTES) : "memory");
        asm volatile("cp.async.bulk.commit_group;" ::: "memory");
        asm volatile("cp.async.bulk.wait_group 0;" ::: "memory");

        // Patch the mixed boundary float4 after the copy has landed.
        if (zb & 3) {
            const int cb = zchunks;                   // mixed chunk's float4 index
            const int c0 = cb << 2;
            float4 v;
            v.x = (c0 + 0 > m) ? 1.f : 0.f;
            v.y = (c0 + 1 > m) ? 1.f : 0.f;
            v.z = (c0 + 2 > m) ? 1.f : 0.f;
            v.w = (c0 + 3 > m) ? 1.f : 0.f;
            reinterpret_cast<float4*>(gdst)[cb] = v;
        }
    }
}

extern "C" void kernel_launch(void* const* d_in, const int* in_sizes, int n_in,
                              void* d_out, int out_size) {
    const int rows = out_size / L_K;                  // 32768

    // m_top: the int32 input with exactly `rows` elements (metadata: d_in[1]).
    const int* m_top = reinterpret_cast<const int*>(d_in[1]);
    for (int i = 0; i < n_in; i++) {
        if (in_sizes[i] == rows) { m_top = reinterpret_cast<const int*>(d_in[i]); break; }
    }

    float* out = reinterpret_cast<float*>(d_out);
    probmask_tma1_kernel<<<rows / ROWS_PER_CTA, THREADS>>>(m_top, out);
}